// round 15
// baseline (speedup 1.0000x reference)
#include <cuda_runtime.h>
#include <cuda_fp16.h>
#include <cstdint>
#include <math.h>

#define BATCH  2
#define SEQ    2048
#define EMBED  1024
#define NHEADS 16
#define HDIM   64
#define MROWS  4096
#define MATSZ  (MROWS*EMBED)     // 4194304
#define WSZ    (EMBED*EMBED)     // 1048576

// ---------------------------------------------------------------------------
// Scratch planes (__device__ globals; allocation-free rule)
// Plain fp16 single-term pipeline (fp32 accumulate in all MMAs).
// ---------------------------------------------------------------------------
__device__ __half g_x[MATSZ];          // x fp16 [M,K]
__device__ __half g_wt[4*WSZ];         // W^T fp16 [N,K] (q,k,v,o)
__device__ __half g_qkv[3*MATSZ];      // q,k,v fp16 [B,H,S,D]
__device__ __half g_a[MATSZ];          // attn out fp16 [M,E]

// ---------------------------------------------------------------------------
// Helpers
// ---------------------------------------------------------------------------
__device__ __forceinline__ uint32_t s2u(const void* p){
    uint32_t a;
    asm("{ .reg .u64 t; cvta.to.shared.u64 t, %1; cvt.u32.u64 %0, t; }" : "=r"(a) : "l"(p));
    return a;
}
__device__ __forceinline__ uint32_t pack2h(float lo, float hi){
    __half2 v = __halves2half2(__float2half(lo), __float2half(hi));
    return *reinterpret_cast<uint32_t*>(&v);
}
__device__ __forceinline__ void ldsm4(uint32_t& r0,uint32_t& r1,uint32_t& r2,uint32_t& r3,uint32_t a){
    asm volatile("ldmatrix.sync.aligned.m8n8.x4.shared.b16 {%0,%1,%2,%3}, [%4];"
        : "=r"(r0),"=r"(r1),"=r"(r2),"=r"(r3) : "r"(a));
}
__device__ __forceinline__ void ldsm4t(uint32_t& r0,uint32_t& r1,uint32_t& r2,uint32_t& r3,uint32_t a){
    asm volatile("ldmatrix.sync.aligned.m8n8.x4.trans.shared.b16 {%0,%1,%2,%3}, [%4];"
        : "=r"(r0),"=r"(r1),"=r"(r2),"=r"(r3) : "r"(a));
}
__device__ __forceinline__ void mma_fp16(float* c, const uint32_t* a, const uint32_t* b){
    asm volatile("mma.sync.aligned.m16n8k16.row.col.f32.f16.f16.f32 "
        "{%0,%1,%2,%3}, {%4,%5,%6,%7}, {%8,%9}, {%0,%1,%2,%3};"
        : "+f"(c[0]),"+f"(c[1]),"+f"(c[2]),"+f"(c[3])
        : "r"(a[0]),"r"(a[1]),"r"(a[2]),"r"(a[3]), "r"(b[0]),"r"(b[1]));
}
__device__ __forceinline__ void cpa16(uint32_t dst, const void* src){
    asm volatile("cp.async.cg.shared.global [%0], [%1], 16;" :: "r"(dst), "l"(src));
}
#define CPCOMMIT() asm volatile("cp.async.commit_group;" ::: "memory")
#define CPWAIT0()  asm volatile("cp.async.wait_group 0;" ::: "memory")

// ---------------------------------------------------------------------------
// Fused prep: z 0..3 -> transpose W (q,k,v,o) to fp16; z 4..7 -> convert x
// block = (32, 8) = 256 threads
// ---------------------------------------------------------------------------
__global__ __launch_bounds__(256) void prep_kernel(
    const float* __restrict__ x,
    const float* __restrict__ Wq, const float* __restrict__ Wk,
    const float* __restrict__ Wv, const float* __restrict__ Wo)
{
    __shared__ float t[32][33];
    const int z = blockIdx.z;
    const int tx = threadIdx.x, ty = threadIdx.y;

    if (z >= 4) {
        int b = (z - 4)*1024 + blockIdx.y*32 + blockIdx.x;
        int i = b*256 + ty*32 + tx;
        float4 v = ((const float4*)x)[i];
        ((uint2*)g_x)[i] = make_uint2(pack2h(v.x, v.y), pack2h(v.z, v.w));
        return;
    }

    const float* W = (z==0)?Wq:(z==1)?Wk:(z==2)?Wv:Wo;
    __half* O = g_wt + (size_t)z*WSZ;
    int nb = blockIdx.x*32, kb = blockIdx.y*32;
    #pragma unroll
    for (int r = 0; r < 4; r++)
        t[ty + r*8][tx] = W[(size_t)(kb + ty + r*8)*EMBED + nb + tx];
    __syncthreads();
    #pragma unroll
    for (int r = 0; r < 4; r++)
        O[(size_t)(nb + ty + r*8)*EMBED + kb + tx] = __float2half(t[tx][ty + r*8]);
}

// ---------------------------------------------------------------------------
// mma.sync fp16 GEMM: D[M,N] = A[M,K] @ B^T[N,K]
// CTA 128x256, 512 threads, 16 warps (4m x 4n), warp 32x64, KC=64, 2-stage.
// mode 0: A = x, B = W_{q,k,v}(z); epilogue -> fp16 qkv planes
// mode 1: A = attn out, B = W_o; epilogue -> fp32 out + bias
// ---------------------------------------------------------------------------
#define GKC 64
#define GNCH (EMBED/GKC)         // 16 chunks
#define GPITCH 144
#define GAPL  (128*GPITCH)       // 18432 (A plane)
#define GBPL  (256*GPITCH)       // 36864 (B plane)
#define GB_OFF GAPL
#define GSTAGE (GAPL + GBPL)     // 55296
#define GSMEM  (2*GSTAGE)        // 110592

__global__ __launch_bounds__(512,1) void gemm_kernel(float* __restrict__ out,
                                                     const float* __restrict__ bias,
                                                     int mode)
{
    extern __shared__ char smg[];
    const uint32_t sb = s2u(smg);
    const int tid = threadIdx.x, l = tid & 31, wid = tid >> 5;
    const int wm = wid >> 2, wn = wid & 3;
    const int m0 = blockIdx.y * 128, n0 = blockIdx.x * 256;
    const int z = blockIdx.z;

    const __half *Ap, *Bp;
    if (mode == 0) { Ap = g_x; Bp = g_wt + (size_t)z*WSZ; }
    else           { Ap = g_a; Bp = g_wt + 3*(size_t)WSZ; }

    auto load_stage = [&](int c){
        const uint32_t sbase = sb + (c & 1)*GSTAGE;
        const int k0 = c * GKC;
        #pragma unroll
        for (int i = 0; i < 2; i++) {        // A: 128 rows x 8 ch = 1024
            int g   = i*512 + tid;
            int row = g >> 3;
            int ch  = g & 7;
            cpa16(sbase + row*GPITCH + ch*16,
                  Ap + (size_t)(m0 + row)*EMBED + k0 + ch*8);
        }
        #pragma unroll
        for (int i = 0; i < 4; i++) {        // B: 256 rows x 8 ch = 2048
            int g   = i*512 + tid;
            int row = (g >> 3) & 255;
            int ch  = g & 7;
            cpa16(sbase + GB_OFF + row*GPITCH + ch*16,
                  Bp + (size_t)(n0 + row)*EMBED + k0 + ch*8);
        }
        CPCOMMIT();
    };

    float acc[2][8][4];
    #pragma unroll
    for (int i = 0; i < 2; i++)
        #pragma unroll
        for (int t = 0; t < 8; t++)
            #pragma unroll
            for (int j = 0; j < 4; j++) acc[i][t][j] = 0.f;

    load_stage(0);
    for (int c = 0; c < GNCH; c++) {
        CPWAIT0();
        __syncthreads();
        if (c + 1 < GNCH) load_stage(c + 1);
        const uint32_t stb = sb + (c & 1)*GSTAGE;
        #pragma unroll
        for (int kk = 0; kk < 4; kk++) {
            uint32_t ah[2][4], bf[8][2];
            #pragma unroll
            for (int i = 0; i < 2; i++) {
                int row = 32*wm + 16*i + (l & 15);
                int ko  = kk*16 + ((l >> 4) << 3);
                uint32_t off = (uint32_t)(row*GPITCH + ko*2);
                ldsm4(ah[i][0],ah[i][1],ah[i][2],ah[i][3], stb + off);
            }
            #pragma unroll
            for (int tp = 0; tp < 4; tp++) {
                int nrow = 64*wn + 16*tp + ((l>>4)<<3) + (l & 7);
                int ko   = kk*16 + (((l>>3)&1) << 3);
                uint32_t off = (uint32_t)(nrow*GPITCH + ko*2);
                ldsm4(bf[2*tp][0],bf[2*tp][1],bf[2*tp+1][0],bf[2*tp+1][1],
                      stb + GB_OFF + off);
            }
            #pragma unroll
            for (int i = 0; i < 2; i++)
                #pragma unroll
                for (int t = 0; t < 8; t++) mma_fp16(acc[i][t], ah[i], bf[t]);
        }
    }

    // epilogue
    if (mode == 1) {
        #pragma unroll
        for (int i = 0; i < 2; i++)
            #pragma unroll
            for (int t = 0; t < 8; t++)
                #pragma unroll
                for (int rr = 0; rr < 2; rr++) {
                    int m = m0 + 32*wm + 16*i + (l>>2) + 8*rr;
                    int n = n0 + 64*wn + 8*t + 2*(l&3);
                    float2 v = make_float2(acc[i][t][2*rr]   + bias[n],
                                           acc[i][t][2*rr+1] + bias[n+1]);
                    *(float2*)&out[(size_t)m*EMBED + n] = v;
                }
    } else {
        __half* oh = g_qkv + (size_t)z*MATSZ;
        const float scl = (z == 0) ? 0.125f : 1.0f;   // fold 1/sqrt(D) into Q
        #pragma unroll
        for (int i = 0; i < 2; i++)
            #pragma unroll
            for (int t = 0; t < 8; t++)
                #pragma unroll
                for (int rr = 0; rr < 2; rr++) {
                    int m = m0 + 32*wm + 16*i + (l>>2) + 8*rr;
                    int n = n0 + 64*wn + 8*t + 2*(l&3);
                    uint32_t h = pack2h(acc[i][t][2*rr]*scl, acc[i][t][2*rr+1]*scl);
                    int b = m >> 11, s = m & 2047, hh = n >> 6, d = n & 63;
                    size_t idx = ((((size_t)b*NHEADS + hh)*SEQ) + s)*HDIM + d;
                    *(uint32_t*)(oh + idx) = h;
                }
    }
}

// ---------------------------------------------------------------------------
// Flash attention, plain fp16. CTA = 64 q-rows; 4 warps; 3 CTAs/SM.
// K-tile = 128 keys. Diagonal-tile skipping: only ntp = ceil((kmax-k0+1)/16)
// active 16-key groups get ldmatrix/MMA/exp. __expf (MUFU) for softmax.
// ---------------------------------------------------------------------------
#define APITCH 144
#define AKPL   (128*APITCH)        // 18432 (one plane: 128 rows)
#define ASTAGE (2*AKPL)            // 36864 (K, V)
#define ASMEM  (2*ASTAGE)          // 73728

__global__ __launch_bounds__(128,3) void attn_kernel()
{
    extern __shared__ char sma[];
    const uint32_t sb = s2u(sma);
    const int tid = threadIdx.x, l = tid & 31, wid = tid >> 5;
    const int qt = 31 - (int)blockIdx.x;        // heavy tiles first
    const int bh = blockIdx.y;
    const int q0 = qt * 64;
    const int nkt = (q0 + 63)/128 + 1;          // 128-key tiles
    const size_t base = (size_t)bh * SEQ * HDIM;
    const __half *Qg = g_qkv + base;
    const __half *Kg = g_qkv + MATSZ + base;
    const __half *Vg = g_qkv + 2*(size_t)MATSZ + base;

    // ---- stream Q plane through stage-0 buffer, extract register frags ----
    #pragma unroll
    for (int i = 0; i < 4; i++) {
        int g = i*128 + tid;
        int row = (g >> 3) & 63, ch = g & 7;
        cpa16(sb + row*APITCH + ch*16, Qg + (size_t)(q0 + row)*HDIM + ch*8);
    }
    CPCOMMIT();
    CPWAIT0();
    __syncthreads();

    uint32_t qf[4][4];
    {
        int row = 16*wid + (l & 15);
        #pragma unroll
        for (int kc = 0; kc < 4; kc++) {
            int ko = kc*16 + ((l >> 4) << 3);
            uint32_t off = (uint32_t)(row*APITCH + ko*2);
            ldsm4(qf[kc][0],qf[kc][1],qf[kc][2],qf[kc][3], sb + off);
        }
    }
    __syncthreads();   // all warps done reading Q before buffer reuse

    auto load_kv = [&](int kt){
        const uint32_t stb = sb + (kt & 1)*ASTAGE;
        const int k0 = kt * 128;
        #pragma unroll
        for (int i = 0; i < 16; i++) {
            int g = i*128 + tid;
            int p = g >> 10, row = (g >> 3) & 127, ch = g & 7;  // p: 0 K, 1 V
            const __half* src = p ? Vg : Kg;
            cpa16(stb + p*AKPL + row*APITCH + ch*16,
                  src + (size_t)(k0 + row)*HDIM + ch*8);
        }
        CPCOMMIT();
    };
    load_kv(0);
    CPWAIT0();
    __syncthreads();

    float o[8][4];
    #pragma unroll
    for (int t = 0; t < 8; t++)
        #pragma unroll
        for (int j = 0; j < 4; j++) o[t][j] = 0.f;
    float mr0 = -1e30f, mr1 = -1e30f, lr0 = 0.f, lr1 = 0.f;
    const int qg0 = q0 + 16*wid + (l >> 2);
    const int qg1 = qg0 + 8;
    const int kmax = q0 + 16*wid + 15;          // warp's max query row

    for (int kt = 0; kt < nkt; kt++) {
        if (kt + 1 < nkt) load_kv(kt + 1);
        const uint32_t stb = sb + (kt & 1)*ASTAGE;
        const int k0 = kt * 128;
        // active 16-key groups for this warp (keys beyond kmax fully masked)
        int ntp = ((kmax - k0) >> 4) + 1;
        if (ntp > 8) ntp = 8;
        const int nt = 2*ntp;                   // active 8-key n8 tiles

        {
            // ---- S = Q K^T over active groups ----
            float s[16][4];
            #pragma unroll
            for (int t = 0; t < 16; t++)
                #pragma unroll
                for (int j = 0; j < 4; j++) s[t][j] = 0.f;
            #pragma unroll
            for (int kc = 0; kc < 4; kc++) {
                #pragma unroll
                for (int half = 0; half < 2; half++) {
                    int ntp_h = ntp - 4*half;
                    if (ntp_h <= 0) continue;
                    if (ntp_h > 4) ntp_h = 4;
                    uint32_t bf[8][2];
                    #pragma unroll 4
                    for (int tp = 0; tp < ntp_h; tp++) {
                        int nrow = half*64 + 16*tp + ((l>>4)<<3) + (l & 7);
                        int ko   = kc*16 + (((l>>3)&1) << 3);
                        uint32_t off = (uint32_t)(nrow*APITCH + ko*2);
                        ldsm4(bf[2*tp][0],bf[2*tp][1],bf[2*tp+1][0],bf[2*tp+1][1], stb + off);
                    }
                    #pragma unroll 8
                    for (int t = 0; t < 2*ntp_h; t++)
                        mma_fp16(s[half*8 + t], qf[kc], bf[t]);
                }
            }
            // ---- causal mask (active tiles near the diagonal) ----
            if (k0 + 8*nt - 1 > qg0) {
                #pragma unroll 16
                for (int t = 0; t < nt; t++) {
                    int kg = k0 + 8*t + 2*(l & 3);
                    if (kg     > qg0) s[t][0] = -1e30f;
                    if (kg + 1 > qg0) s[t][1] = -1e30f;
                    if (kg     > qg1) s[t][2] = -1e30f;
                    if (kg + 1 > qg1) s[t][3] = -1e30f;
                }
            }
            // ---- online softmax over active tiles (rows qg0, qg1) ----
            float mx0 = -1e30f, mx1 = -1e30f;
            #pragma unroll 16
            for (int t = 0; t < nt; t++) {
                mx0 = fmaxf(mx0, fmaxf(s[t][0], s[t][1]));
                mx1 = fmaxf(mx1, fmaxf(s[t][2], s[t][3]));
            }
            mx0 = fmaxf(mx0, __shfl_xor_sync(0xffffffffu, mx0, 1));
            mx0 = fmaxf(mx0, __shfl_xor_sync(0xffffffffu, mx0, 2));
            mx1 = fmaxf(mx1, __shfl_xor_sync(0xffffffffu, mx1, 1));
            mx1 = fmaxf(mx1, __shfl_xor_sync(0xffffffffu, mx1, 2));
            float mn0 = fmaxf(mr0, mx0), mn1 = fmaxf(mr1, mx1);
            float a0 = __expf(mr0 - mn0), a1 = __expf(mr1 - mn1);
            mr0 = mn0; mr1 = mn1;
            float rs0 = 0.f, rs1 = 0.f;
            #pragma unroll 16
            for (int t = 0; t < nt; t++) {
                s[t][0] = __expf(s[t][0] - mn0);
                s[t][1] = __expf(s[t][1] - mn0);
                s[t][2] = __expf(s[t][2] - mn1);
                s[t][3] = __expf(s[t][3] - mn1);
                rs0 += s[t][0] + s[t][1];
                rs1 += s[t][2] + s[t][3];
            }
            rs0 += __shfl_xor_sync(0xffffffffu, rs0, 1);
            rs0 += __shfl_xor_sync(0xffffffffu, rs0, 2);
            rs1 += __shfl_xor_sync(0xffffffffu, rs1, 1);
            rs1 += __shfl_xor_sync(0xffffffffu, rs1, 2);
            lr0 = lr0*a0 + rs0;
            lr1 = lr1*a1 + rs1;
            #pragma unroll
            for (int t = 0; t < 8; t++) {
                o[t][0] *= a0; o[t][1] *= a0; o[t][2] *= a1; o[t][3] *= a1;
            }
            // ---- P -> fp16 A-fragments (active kc only) ----
            uint32_t ph[8][4];
            #pragma unroll 8
            for (int kc = 0; kc < ntp; kc++) {
                int t0 = 2*kc, t1 = t0 + 1;
                ph[kc][0] = pack2h(s[t0][0], s[t0][1]);
                ph[kc][1] = pack2h(s[t0][2], s[t0][3]);
                ph[kc][2] = pack2h(s[t1][0], s[t1][1]);
                ph[kc][3] = pack2h(s[t1][2], s[t1][3]);
            }
            // ---- O += P V over active key groups, V via ldmatrix.trans ----
            #pragma unroll 8
            for (int kc = 0; kc < ntp; kc++) {
                uint32_t vf[8][2];
                #pragma unroll
                for (int tp = 0; tp < 4; tp++) {
                    int row = kc*16 + ((l>>3)&1)*8 + (l & 7);
                    int co  = 16*tp + ((l >> 4) << 3);
                    uint32_t off = (uint32_t)(row*APITCH + co*2);
                    ldsm4t(vf[2*tp][0],vf[2*tp][1],vf[2*tp+1][0],vf[2*tp+1][1], stb + AKPL + off);
                }
                #pragma unroll
                for (int t = 0; t < 8; t++) mma_fp16(o[t], ph[kc], vf[t]);
            }
        }
        if (kt + 1 < nkt) { CPWAIT0(); __syncthreads(); }
    }

    // ---- epilogue: normalize, write fp16 plane [B,S,E] ----
    const float inv0 = 1.f / lr0, inv1 = 1.f / lr1;
    const int b = bh >> 4, h = bh & 15;
    const int s0 = qg0, s1 = qg1;
    #pragma unroll
    for (int t = 0; t < 8; t++) {
        int d = 8*t + 2*(l & 3);
        int e = h*HDIM + d;
        *(uint32_t*)(g_a + ((size_t)b*SEQ + s0)*EMBED + e) =
            pack2h(o[t][0]*inv0, o[t][1]*inv0);
        *(uint32_t*)(g_a + ((size_t)b*SEQ + s1)*EMBED + e) =
            pack2h(o[t][2]*inv1, o[t][3]*inv1);
    }
}

// ---------------------------------------------------------------------------
extern "C" void kernel_launch(void* const* d_in, const int* in_sizes, int n_in,
                              void* d_out, int out_size)
{
    const float* x  = (const float*)d_in[0];
    const float* Wq = (const float*)d_in[1];
    const float* Wk = (const float*)d_in[2];
    const float* Wv = (const float*)d_in[3];
    const float* Wo = (const float*)d_in[4];
    const float* bo = (const float*)d_in[5];
    float* out = (float*)d_out;

    cudaFuncSetAttribute(gemm_kernel, cudaFuncAttributeMaxDynamicSharedMemorySize, GSMEM);
    cudaFuncSetAttribute(attn_kernel, cudaFuncAttributeMaxDynamicSharedMemorySize, ASMEM);

    prep_kernel<<<dim3(32, 32, 8), dim3(32, 8)>>>(x, Wq, Wk, Wv, Wo);

    gemm_kernel<<<dim3(4, 32, 3), 512, GSMEM>>>(nullptr, nullptr, 0);  // QKV
    attn_kernel<<<dim3(32, 32), 128, ASMEM>>>();                       // attention
    gemm_kernel<<<dim3(4, 32, 1), 512, GSMEM>>>(out, bo, 1);           // O-proj
}

// round 16
// speedup vs baseline: 3.2815x; 3.2815x over previous
#include <cuda_runtime.h>
#include <cuda_fp16.h>
#include <cstdint>
#include <math.h>

#define BATCH  2
#define SEQ    2048
#define EMBED  1024
#define NHEADS 16
#define HDIM   64
#define MROWS  4096
#define MATSZ  (MROWS*EMBED)     // 4194304
#define WSZ    (EMBED*EMBED)     // 1048576

// ---------------------------------------------------------------------------
// Scratch planes (__device__ globals; allocation-free rule)
// Plain fp16 single-term pipeline (fp32 accumulate in all MMAs).
// ---------------------------------------------------------------------------
__device__ __half g_x[MATSZ];          // x fp16 [M,K]
__device__ __half g_wt[4*WSZ];         // W^T fp16 [N,K] (q,k,v,o)
__device__ __half g_qkv[3*MATSZ];      // q,k,v fp16 [B,H,S,D]
__device__ __half g_a[MATSZ];          // attn out fp16 [M,E]

// ---------------------------------------------------------------------------
// Helpers
// ---------------------------------------------------------------------------
__device__ __forceinline__ uint32_t s2u(const void* p){
    uint32_t a;
    asm("{ .reg .u64 t; cvta.to.shared.u64 t, %1; cvt.u32.u64 %0, t; }" : "=r"(a) : "l"(p));
    return a;
}
__device__ __forceinline__ uint32_t pack2h(float lo, float hi){
    __half2 v = __halves2half2(__float2half(lo), __float2half(hi));
    return *reinterpret_cast<uint32_t*>(&v);
}
__device__ __forceinline__ void ldsm4(uint32_t& r0,uint32_t& r1,uint32_t& r2,uint32_t& r3,uint32_t a){
    asm volatile("ldmatrix.sync.aligned.m8n8.x4.shared.b16 {%0,%1,%2,%3}, [%4];"
        : "=r"(r0),"=r"(r1),"=r"(r2),"=r"(r3) : "r"(a));
}
__device__ __forceinline__ void ldsm4t(uint32_t& r0,uint32_t& r1,uint32_t& r2,uint32_t& r3,uint32_t a){
    asm volatile("ldmatrix.sync.aligned.m8n8.x4.trans.shared.b16 {%0,%1,%2,%3}, [%4];"
        : "=r"(r0),"=r"(r1),"=r"(r2),"=r"(r3) : "r"(a));
}
__device__ __forceinline__ void mma_fp16(float* c, const uint32_t* a, const uint32_t* b){
    asm volatile("mma.sync.aligned.m16n8k16.row.col.f32.f16.f16.f32 "
        "{%0,%1,%2,%3}, {%4,%5,%6,%7}, {%8,%9}, {%0,%1,%2,%3};"
        : "+f"(c[0]),"+f"(c[1]),"+f"(c[2]),"+f"(c[3])
        : "r"(a[0]),"r"(a[1]),"r"(a[2]),"r"(a[3]), "r"(b[0]),"r"(b[1]));
}
__device__ __forceinline__ void cpa16(uint32_t dst, const void* src){
    asm volatile("cp.async.cg.shared.global [%0], [%1], 16;" :: "r"(dst), "l"(src));
}
#define CPCOMMIT() asm volatile("cp.async.commit_group;" ::: "memory")
#define CPWAIT0()  asm volatile("cp.async.wait_group 0;" ::: "memory")

// ---------------------------------------------------------------------------
// Fused prep: z 0..3 -> transpose W (q,k,v,o) to fp16; z 4..7 -> convert x
// block = (32, 8) = 256 threads
// ---------------------------------------------------------------------------
__global__ __launch_bounds__(256) void prep_kernel(
    const float* __restrict__ x,
    const float* __restrict__ Wq, const float* __restrict__ Wk,
    const float* __restrict__ Wv, const float* __restrict__ Wo)
{
    __shared__ float t[32][33];
    const int z = blockIdx.z;
    const int tx = threadIdx.x, ty = threadIdx.y;

    if (z >= 4) {
        int b = (z - 4)*1024 + blockIdx.y*32 + blockIdx.x;
        int i = b*256 + ty*32 + tx;
        float4 v = ((const float4*)x)[i];
        ((uint2*)g_x)[i] = make_uint2(pack2h(v.x, v.y), pack2h(v.z, v.w));
        return;
    }

    const float* W = (z==0)?Wq:(z==1)?Wk:(z==2)?Wv:Wo;
    __half* O = g_wt + (size_t)z*WSZ;
    int nb = blockIdx.x*32, kb = blockIdx.y*32;
    #pragma unroll
    for (int r = 0; r < 4; r++)
        t[ty + r*8][tx] = W[(size_t)(kb + ty + r*8)*EMBED + nb + tx];
    __syncthreads();
    #pragma unroll
    for (int r = 0; r < 4; r++)
        O[(size_t)(nb + ty + r*8)*EMBED + kb + tx] = __float2half(t[tx][ty + r*8]);
}

// ---------------------------------------------------------------------------
// mma.sync fp16 GEMM: D[M,N] = A[M,K] @ B^T[N,K]
// CTA 128x256, 512 threads, 16 warps (4m x 4n), warp 32x64, KC=64, 2-stage.
// mode 0: A = x, B = W_{q,k,v}(z); epilogue -> fp16 qkv planes
// mode 1: A = attn out, B = W_o; epilogue -> fp32 out + bias
// ---------------------------------------------------------------------------
#define GKC 64
#define GNCH (EMBED/GKC)         // 16 chunks
#define GPITCH 144
#define GAPL  (128*GPITCH)       // 18432 (A plane)
#define GBPL  (256*GPITCH)       // 36864 (B plane)
#define GB_OFF GAPL
#define GSTAGE (GAPL + GBPL)     // 55296
#define GSMEM  (2*GSTAGE)        // 110592

__global__ __launch_bounds__(512,1) void gemm_kernel(float* __restrict__ out,
                                                     const float* __restrict__ bias,
                                                     int mode)
{
    extern __shared__ char smg[];
    const uint32_t sb = s2u(smg);
    const int tid = threadIdx.x, l = tid & 31, wid = tid >> 5;
    const int wm = wid >> 2, wn = wid & 3;
    const int m0 = blockIdx.y * 128, n0 = blockIdx.x * 256;
    const int z = blockIdx.z;

    const __half *Ap, *Bp;
    if (mode == 0) { Ap = g_x; Bp = g_wt + (size_t)z*WSZ; }
    else           { Ap = g_a; Bp = g_wt + 3*(size_t)WSZ; }

    auto load_stage = [&](int c){
        const uint32_t sbase = sb + (c & 1)*GSTAGE;
        const int k0 = c * GKC;
        #pragma unroll
        for (int i = 0; i < 2; i++) {        // A: 128 rows x 8 ch = 1024
            int g   = i*512 + tid;
            int row = g >> 3;
            int ch  = g & 7;
            cpa16(sbase + row*GPITCH + ch*16,
                  Ap + (size_t)(m0 + row)*EMBED + k0 + ch*8);
        }
        #pragma unroll
        for (int i = 0; i < 4; i++) {        // B: 256 rows x 8 ch = 2048
            int g   = i*512 + tid;
            int row = (g >> 3) & 255;
            int ch  = g & 7;
            cpa16(sbase + GB_OFF + row*GPITCH + ch*16,
                  Bp + (size_t)(n0 + row)*EMBED + k0 + ch*8);
        }
        CPCOMMIT();
    };

    float acc[2][8][4];
    #pragma unroll
    for (int i = 0; i < 2; i++)
        #pragma unroll
        for (int t = 0; t < 8; t++)
            #pragma unroll
            for (int j = 0; j < 4; j++) acc[i][t][j] = 0.f;

    load_stage(0);
    for (int c = 0; c < GNCH; c++) {
        CPWAIT0();
        __syncthreads();
        if (c + 1 < GNCH) load_stage(c + 1);
        const uint32_t stb = sb + (c & 1)*GSTAGE;
        #pragma unroll
        for (int kk = 0; kk < 4; kk++) {
            uint32_t ah[2][4], bf[8][2];
            #pragma unroll
            for (int i = 0; i < 2; i++) {
                int row = 32*wm + 16*i + (l & 15);
                int ko  = kk*16 + ((l >> 4) << 3);
                uint32_t off = (uint32_t)(row*GPITCH + ko*2);
                ldsm4(ah[i][0],ah[i][1],ah[i][2],ah[i][3], stb + off);
            }
            #pragma unroll
            for (int tp = 0; tp < 4; tp++) {
                int nrow = 64*wn + 16*tp + ((l>>4)<<3) + (l & 7);
                int ko   = kk*16 + (((l>>3)&1) << 3);
                uint32_t off = (uint32_t)(nrow*GPITCH + ko*2);
                ldsm4(bf[2*tp][0],bf[2*tp][1],bf[2*tp+1][0],bf[2*tp+1][1],
                      stb + GB_OFF + off);
            }
            #pragma unroll
            for (int i = 0; i < 2; i++)
                #pragma unroll
                for (int t = 0; t < 8; t++) mma_fp16(acc[i][t], ah[i], bf[t]);
        }
    }

    // epilogue
    if (mode == 1) {
        #pragma unroll
        for (int i = 0; i < 2; i++)
            #pragma unroll
            for (int t = 0; t < 8; t++)
                #pragma unroll
                for (int rr = 0; rr < 2; rr++) {
                    int m = m0 + 32*wm + 16*i + (l>>2) + 8*rr;
                    int n = n0 + 64*wn + 8*t + 2*(l&3);
                    float2 v = make_float2(acc[i][t][2*rr]   + bias[n],
                                           acc[i][t][2*rr+1] + bias[n+1]);
                    *(float2*)&out[(size_t)m*EMBED + n] = v;
                }
    } else {
        __half* oh = g_qkv + (size_t)z*MATSZ;
        const float scl = (z == 0) ? 0.125f : 1.0f;   // fold 1/sqrt(D) into Q
        #pragma unroll
        for (int i = 0; i < 2; i++)
            #pragma unroll
            for (int t = 0; t < 8; t++)
                #pragma unroll
                for (int rr = 0; rr < 2; rr++) {
                    int m = m0 + 32*wm + 16*i + (l>>2) + 8*rr;
                    int n = n0 + 64*wn + 8*t + 2*(l&3);
                    uint32_t h = pack2h(acc[i][t][2*rr]*scl, acc[i][t][2*rr+1]*scl);
                    int b = m >> 11, s = m & 2047, hh = n >> 6, d = n & 63;
                    size_t idx = ((((size_t)b*NHEADS + hh)*SEQ) + s)*HDIM + d;
                    *(uint32_t*)(oh + idx) = h;
                }
    }
}

// ---------------------------------------------------------------------------
// Flash attention, plain fp16. CTA = 64 q-rows; 4 warps; 3 CTAs/SM.
// K-tile = 128 keys, all loops statically unrolled (no dynamic reg indexing).
// __expf (MUFU) softmax; fp32 accumulate.
// ---------------------------------------------------------------------------
#define APITCH 144
#define AKPL   (128*APITCH)        // 18432 (one plane: 128 rows)
#define ASTAGE (2*AKPL)            // 36864 (K, V)
#define ASMEM  (2*ASTAGE)          // 73728

__global__ __launch_bounds__(128,3) void attn_kernel()
{
    extern __shared__ char sma[];
    const uint32_t sb = s2u(sma);
    const int tid = threadIdx.x, l = tid & 31, wid = tid >> 5;
    const int qt = 31 - (int)blockIdx.x;        // heavy tiles first
    const int bh = blockIdx.y;
    const int q0 = qt * 64;
    const int nkt = (q0 + 63)/128 + 1;          // 128-key tiles
    const size_t base = (size_t)bh * SEQ * HDIM;
    const __half *Qg = g_qkv + base;
    const __half *Kg = g_qkv + MATSZ + base;
    const __half *Vg = g_qkv + 2*(size_t)MATSZ + base;

    // ---- stream Q plane through stage-0 buffer, extract register frags ----
    #pragma unroll
    for (int i = 0; i < 4; i++) {
        int g = i*128 + tid;
        int row = (g >> 3) & 63, ch = g & 7;
        cpa16(sb + row*APITCH + ch*16, Qg + (size_t)(q0 + row)*HDIM + ch*8);
    }
    CPCOMMIT();
    CPWAIT0();
    __syncthreads();

    uint32_t qf[4][4];
    {
        int row = 16*wid + (l & 15);
        #pragma unroll
        for (int kc = 0; kc < 4; kc++) {
            int ko = kc*16 + ((l >> 4) << 3);
            uint32_t off = (uint32_t)(row*APITCH + ko*2);
            ldsm4(qf[kc][0],qf[kc][1],qf[kc][2],qf[kc][3], sb + off);
        }
    }
    __syncthreads();   // all warps done reading Q before buffer reuse

    auto load_kv = [&](int kt){
        const uint32_t stb = sb + (kt & 1)*ASTAGE;
        const int k0 = kt * 128;
        #pragma unroll
        for (int i = 0; i < 16; i++) {
            int g = i*128 + tid;
            int p = g >> 10, row = (g >> 3) & 127, ch = g & 7;  // p: 0 K, 1 V
            const __half* src = p ? Vg : Kg;
            cpa16(stb + p*AKPL + row*APITCH + ch*16,
                  src + (size_t)(k0 + row)*HDIM + ch*8);
        }
        CPCOMMIT();
    };
    load_kv(0);
    CPWAIT0();
    __syncthreads();

    float o[8][4];
    #pragma unroll
    for (int t = 0; t < 8; t++)
        #pragma unroll
        for (int j = 0; j < 4; j++) o[t][j] = 0.f;
    float mr0 = -1e30f, mr1 = -1e30f, lr0 = 0.f, lr1 = 0.f;
    const int qg0 = q0 + 16*wid + (l >> 2);
    const int qg1 = qg0 + 8;

    for (int kt = 0; kt < nkt; kt++) {
        if (kt + 1 < nkt) load_kv(kt + 1);
        const uint32_t stb = sb + (kt & 1)*ASTAGE;
        const int k0 = kt * 128;

        {
            // ---- S = Q K^T over 128 keys (16 n8-tiles) ----
            float s[16][4];
            #pragma unroll
            for (int t = 0; t < 16; t++)
                #pragma unroll
                for (int j = 0; j < 4; j++) s[t][j] = 0.f;
            #pragma unroll
            for (int kc = 0; kc < 4; kc++) {
                #pragma unroll
                for (int half = 0; half < 2; half++) {   // bf regs capped at 16
                    uint32_t bf[8][2];
                    #pragma unroll
                    for (int tp = 0; tp < 4; tp++) {
                        int nrow = half*64 + 16*tp + ((l>>4)<<3) + (l & 7);
                        int ko   = kc*16 + (((l>>3)&1) << 3);
                        uint32_t off = (uint32_t)(nrow*APITCH + ko*2);
                        ldsm4(bf[2*tp][0],bf[2*tp][1],bf[2*tp+1][0],bf[2*tp+1][1], stb + off);
                    }
                    #pragma unroll
                    for (int t = 0; t < 8; t++) mma_fp16(s[half*8 + t], qf[kc], bf[t]);
                }
            }
            // ---- causal mask (only near diagonal) ----
            if (k0 + 127 > qg0) {
                #pragma unroll
                for (int t = 0; t < 16; t++) {
                    int kg = k0 + 8*t + 2*(l & 3);
                    if (kg     > qg0) s[t][0] = -1e30f;
                    if (kg + 1 > qg0) s[t][1] = -1e30f;
                    if (kg     > qg1) s[t][2] = -1e30f;
                    if (kg + 1 > qg1) s[t][3] = -1e30f;
                }
            }
            // ---- online softmax (rows qg0, qg1), __expf on MUFU ----
            float mx0 = -1e30f, mx1 = -1e30f;
            #pragma unroll
            for (int t = 0; t < 16; t++) {
                mx0 = fmaxf(mx0, fmaxf(s[t][0], s[t][1]));
                mx1 = fmaxf(mx1, fmaxf(s[t][2], s[t][3]));
            }
            mx0 = fmaxf(mx0, __shfl_xor_sync(0xffffffffu, mx0, 1));
            mx0 = fmaxf(mx0, __shfl_xor_sync(0xffffffffu, mx0, 2));
            mx1 = fmaxf(mx1, __shfl_xor_sync(0xffffffffu, mx1, 1));
            mx1 = fmaxf(mx1, __shfl_xor_sync(0xffffffffu, mx1, 2));
            float mn0 = fmaxf(mr0, mx0), mn1 = fmaxf(mr1, mx1);
            float a0 = __expf(mr0 - mn0), a1 = __expf(mr1 - mn1);
            mr0 = mn0; mr1 = mn1;
            float rs0 = 0.f, rs1 = 0.f;
            #pragma unroll
            for (int t = 0; t < 16; t++) {
                s[t][0] = __expf(s[t][0] - mn0);
                s[t][1] = __expf(s[t][1] - mn0);
                s[t][2] = __expf(s[t][2] - mn1);
                s[t][3] = __expf(s[t][3] - mn1);
                rs0 += s[t][0] + s[t][1];
                rs1 += s[t][2] + s[t][3];
            }
            rs0 += __shfl_xor_sync(0xffffffffu, rs0, 1);
            rs0 += __shfl_xor_sync(0xffffffffu, rs0, 2);
            rs1 += __shfl_xor_sync(0xffffffffu, rs1, 1);
            rs1 += __shfl_xor_sync(0xffffffffu, rs1, 2);
            lr0 = lr0*a0 + rs0;
            lr1 = lr1*a1 + rs1;
            #pragma unroll
            for (int t = 0; t < 8; t++) {
                o[t][0] *= a0; o[t][1] *= a0; o[t][2] *= a1; o[t][3] *= a1;
            }
            // ---- P -> fp16 A-fragments (registers only), 8 k16 chunks ----
            uint32_t ph[8][4];
            #pragma unroll
            for (int kc = 0; kc < 8; kc++) {
                int t0 = 2*kc, t1 = t0 + 1;
                ph[kc][0] = pack2h(s[t0][0], s[t0][1]);
                ph[kc][1] = pack2h(s[t0][2], s[t0][3]);
                ph[kc][2] = pack2h(s[t1][0], s[t1][1]);
                ph[kc][3] = pack2h(s[t1][2], s[t1][3]);
            }
            // ---- O += P V over 128 keys, V via ldmatrix.trans ----
            #pragma unroll
            for (int kc = 0; kc < 8; kc++) {
                uint32_t vf[8][2];
                #pragma unroll
                for (int tp = 0; tp < 4; tp++) {
                    int row = kc*16 + ((l>>3)&1)*8 + (l & 7);
                    int co  = 16*tp + ((l >> 4) << 3);
                    uint32_t off = (uint32_t)(row*APITCH + co*2);
                    ldsm4t(vf[2*tp][0],vf[2*tp][1],vf[2*tp+1][0],vf[2*tp+1][1], stb + AKPL + off);
                }
                #pragma unroll
                for (int t = 0; t < 8; t++) mma_fp16(o[t], ph[kc], vf[t]);
            }
        }
        if (kt + 1 < nkt) { CPWAIT0(); __syncthreads(); }
    }

    // ---- epilogue: normalize, write fp16 plane [B,S,E] ----
    const float inv0 = 1.f / lr0, inv1 = 1.f / lr1;
    const int b = bh >> 4, h = bh & 15;
    const int s0 = qg0, s1 = qg1;
    #pragma unroll
    for (int t = 0; t < 8; t++) {
        int d = 8*t + 2*(l & 3);
        int e = h*HDIM + d;
        *(uint32_t*)(g_a + ((size_t)b*SEQ + s0)*EMBED + e) =
            pack2h(o[t][0]*inv0, o[t][1]*inv0);
        *(uint32_t*)(g_a + ((size_t)b*SEQ + s1)*EMBED + e) =
            pack2h(o[t][2]*inv1, o[t][3]*inv1);
    }
}

// ---------------------------------------------------------------------------
extern "C" void kernel_launch(void* const* d_in, const int* in_sizes, int n_in,
                              void* d_out, int out_size)
{
    const float* x  = (const float*)d_in[0];
    const float* Wq = (const float*)d_in[1];
    const float* Wk = (const float*)d_in[2];
    const float* Wv = (const float*)d_in[3];
    const float* Wo = (const float*)d_in[4];
    const float* bo = (const float*)d_in[5];
    float* out = (float*)d_out;

    cudaFuncSetAttribute(gemm_kernel, cudaFuncAttributeMaxDynamicSharedMemorySize, GSMEM);
    cudaFuncSetAttribute(attn_kernel, cudaFuncAttributeMaxDynamicSharedMemorySize, ASMEM);

    prep_kernel<<<dim3(32, 32, 8), dim3(32, 8)>>>(x, Wq, Wk, Wv, Wo);

    gemm_kernel<<<dim3(4, 32, 3), 512, GSMEM>>>(nullptr, nullptr, 0);  // QKV
    attn_kernel<<<dim3(32, 32), 128, ASMEM>>>();                       // attention
    gemm_kernel<<<dim3(4, 32, 1), 512, GSMEM>>>(out, bo, 1);           // O-proj
}

// round 17
// speedup vs baseline: 3.4048x; 1.0376x over previous
#include <cuda_runtime.h>
#include <cuda_fp16.h>
#include <cstdint>
#include <math.h>

#define BATCH  2
#define SEQ    2048
#define EMBED  1024
#define NHEADS 16
#define HDIM   64
#define MROWS  4096
#define MATSZ  (MROWS*EMBED)     // 4194304
#define WSZ    (EMBED*EMBED)     // 1048576

// ---------------------------------------------------------------------------
// Scratch planes (__device__ globals; allocation-free rule)
// fp16 single-term pipeline; W kept in native [K,N] order (no transpose).
// ---------------------------------------------------------------------------
__device__ __half g_x[MATSZ];          // x fp16 [M,K]
__device__ __half g_wt[4*WSZ];         // W fp16 [K,N] (q,k,v,o)
__device__ __half g_qkv[3*MATSZ];      // q,k,v fp16 [B,H,S,D]
__device__ __half g_a[MATSZ];          // attn out fp16 [M,E]

// ---------------------------------------------------------------------------
// Helpers
// ---------------------------------------------------------------------------
__device__ __forceinline__ uint32_t s2u(const void* p){
    uint32_t a;
    asm("{ .reg .u64 t; cvta.to.shared.u64 t, %1; cvt.u32.u64 %0, t; }" : "=r"(a) : "l"(p));
    return a;
}
__device__ __forceinline__ uint32_t pack2h(float lo, float hi){
    __half2 v = __halves2half2(__float2half(lo), __float2half(hi));
    return *reinterpret_cast<uint32_t*>(&v);
}
__device__ __forceinline__ float ex2(float x){
    float r; asm("ex2.approx.f32 %0, %1;" : "=f"(r) : "f"(x)); return r;
}
__device__ __forceinline__ void ldsm4(uint32_t& r0,uint32_t& r1,uint32_t& r2,uint32_t& r3,uint32_t a){
    asm volatile("ldmatrix.sync.aligned.m8n8.x4.shared.b16 {%0,%1,%2,%3}, [%4];"
        : "=r"(r0),"=r"(r1),"=r"(r2),"=r"(r3) : "r"(a));
}
__device__ __forceinline__ void ldsm4t(uint32_t& r0,uint32_t& r1,uint32_t& r2,uint32_t& r3,uint32_t a){
    asm volatile("ldmatrix.sync.aligned.m8n8.x4.trans.shared.b16 {%0,%1,%2,%3}, [%4];"
        : "=r"(r0),"=r"(r1),"=r"(r2),"=r"(r3) : "r"(a));
}
__device__ __forceinline__ void mma_fp16(float* c, const uint32_t* a, const uint32_t* b){
    asm volatile("mma.sync.aligned.m16n8k16.row.col.f32.f16.f16.f32 "
        "{%0,%1,%2,%3}, {%4,%5,%6,%7}, {%8,%9}, {%0,%1,%2,%3};"
        : "+f"(c[0]),"+f"(c[1]),"+f"(c[2]),"+f"(c[3])
        : "r"(a[0]),"r"(a[1]),"r"(a[2]),"r"(a[3]), "r"(b[0]),"r"(b[1]));
}
__device__ __forceinline__ void cpa16(uint32_t dst, const void* src){
    asm volatile("cp.async.cg.shared.global [%0], [%1], 16;" :: "r"(dst), "l"(src));
}
#define CPCOMMIT() asm volatile("cp.async.commit_group;" ::: "memory")
#define CPWAIT0()  asm volatile("cp.async.wait_group 0;" ::: "memory")

// ---------------------------------------------------------------------------
// Fused prep (all streaming converts): z 0..3 -> W_z fp32->fp16 ([K,N] kept);
// z 4..7 -> x fp32->fp16. block = (32,8) = 256 threads, 1 float4 per thread.
// ---------------------------------------------------------------------------
__global__ __launch_bounds__(256) void prep_kernel(
    const float* __restrict__ x,
    const float* __restrict__ Wq, const float* __restrict__ Wk,
    const float* __restrict__ Wv, const float* __restrict__ Wo)
{
    const int z = blockIdx.z;
    const int tx = threadIdx.x, ty = threadIdx.y;
    const int blk = blockIdx.y*32 + blockIdx.x;

    if (z >= 4) {
        int i = ((z - 4)*1024 + blk)*256 + ty*32 + tx;   // 1M float4 total
        float4 v = ((const float4*)x)[i];
        ((uint2*)g_x)[i] = make_uint2(pack2h(v.x, v.y), pack2h(v.z, v.w));
        return;
    }
    const float* W = (z==0)?Wq:(z==1)?Wk:(z==2)?Wv:Wo;
    __half* O = g_wt + (size_t)z*WSZ;
    int i = blk*256 + ty*32 + tx;                        // 256K float4 per mat
    float4 v = ((const float4*)W)[i];
    ((uint2*)O)[i] = make_uint2(pack2h(v.x, v.y), pack2h(v.z, v.w));
}

// ---------------------------------------------------------------------------
// mma.sync fp16 GEMM: D[M,N] = A[M,K] @ W[K,N]
// CTA 128x256, 512 threads, 16 warps (4m x 4n), warp 32x64, KC=64, 2-stage.
// B tiles stored [k][n] in smem; B fragments via ldmatrix.trans (attn-V pattern).
// mode 0: A = x, B = W_{q,k,v}(z); epilogue -> fp16 qkv planes (Q pre-scaled
//         by 0.125*log2(e) so attention softmax can use bare ex2).
// mode 1: A = attn out, B = W_o; epilogue -> fp32 out + bias
// ---------------------------------------------------------------------------
#define GKC 64
#define GNCH (EMBED/GKC)         // 16 chunks
#define GPITCH 144               // A row pitch (64 k * 2B + pad)
#define GBPITCH 528              // B row pitch (256 n * 2B + pad)
#define GAPL  (128*GPITCH)       // 18432 (A tile)
#define GBPL  (64*GBPITCH)       // 33792 (B tile: 64 k-rows x 256 n)
#define GB_OFF GAPL
#define GSTAGE (GAPL + GBPL)     // 52224
#define GSMEM  (2*GSTAGE)        // 104448

__global__ __launch_bounds__(512,1) void gemm_kernel(float* __restrict__ out,
                                                     const float* __restrict__ bias,
                                                     int mode)
{
    extern __shared__ char smg[];
    const uint32_t sb = s2u(smg);
    const int tid = threadIdx.x, l = tid & 31, wid = tid >> 5;
    const int wm = wid >> 2, wn = wid & 3;
    const int m0 = blockIdx.y * 128, n0 = blockIdx.x * 256;
    const int z = blockIdx.z;

    const __half *Ap, *Bp;
    if (mode == 0) { Ap = g_x; Bp = g_wt + (size_t)z*WSZ; }
    else           { Ap = g_a; Bp = g_wt + 3*(size_t)WSZ; }

    auto load_stage = [&](int c){
        const uint32_t sbase = sb + (c & 1)*GSTAGE;
        const int k0 = c * GKC;
        #pragma unroll
        for (int i = 0; i < 2; i++) {        // A: 128 rows x 8 ch = 1024
            int g   = i*512 + tid;
            int row = g >> 3;
            int ch  = g & 7;
            cpa16(sbase + row*GPITCH + ch*16,
                  Ap + (size_t)(m0 + row)*EMBED + k0 + ch*8);
        }
        #pragma unroll
        for (int i = 0; i < 4; i++) {        // B: 64 k-rows x 32 ch = 2048
            int g   = i*512 + tid;
            int row = g >> 5;                // 0..63
            int ch  = g & 31;
            cpa16(sbase + GB_OFF + row*GBPITCH + ch*16,
                  Bp + (size_t)(k0 + row)*EMBED + n0 + ch*8);
        }
        CPCOMMIT();
    };

    float acc[2][8][4];
    #pragma unroll
    for (int i = 0; i < 2; i++)
        #pragma unroll
        for (int t = 0; t < 8; t++)
            #pragma unroll
            for (int j = 0; j < 4; j++) acc[i][t][j] = 0.f;

    load_stage(0);
    for (int c = 0; c < GNCH; c++) {
        CPWAIT0();
        __syncthreads();
        if (c + 1 < GNCH) load_stage(c + 1);
        const uint32_t stb = sb + (c & 1)*GSTAGE;
        #pragma unroll
        for (int kk = 0; kk < 4; kk++) {
            uint32_t ah[2][4], bf[8][2];
            #pragma unroll
            for (int i = 0; i < 2; i++) {
                int row = 32*wm + 16*i + (l & 15);
                int ko  = kk*16 + ((l >> 4) << 3);
                uint32_t off = (uint32_t)(row*GPITCH + ko*2);
                ldsm4(ah[i][0],ah[i][1],ah[i][2],ah[i][3], stb + off);
            }
            #pragma unroll
            for (int tp = 0; tp < 4; tp++) {   // B frags: trans from [k][n]
                int row = kk*16 + ((l>>3)&1)*8 + (l & 7);
                int col = 64*wn + 16*tp + ((l >> 4) << 3);
                uint32_t off = (uint32_t)(row*GBPITCH + col*2);
                ldsm4t(bf[2*tp][0],bf[2*tp][1],bf[2*tp+1][0],bf[2*tp+1][1],
                       stb + GB_OFF + off);
            }
            #pragma unroll
            for (int i = 0; i < 2; i++)
                #pragma unroll
                for (int t = 0; t < 8; t++) mma_fp16(acc[i][t], ah[i], bf[t]);
        }
    }

    // epilogue
    if (mode == 1) {
        #pragma unroll
        for (int i = 0; i < 2; i++)
            #pragma unroll
            for (int t = 0; t < 8; t++)
                #pragma unroll
                for (int rr = 0; rr < 2; rr++) {
                    int m = m0 + 32*wm + 16*i + (l>>2) + 8*rr;
                    int n = n0 + 64*wn + 8*t + 2*(l&3);
                    float2 v = make_float2(acc[i][t][2*rr]   + bias[n],
                                           acc[i][t][2*rr+1] + bias[n+1]);
                    *(float2*)&out[(size_t)m*EMBED + n] = v;
                }
    } else {
        __half* oh = g_qkv + (size_t)z*MATSZ;
        // Q: fold 1/sqrt(D) * log2(e) so softmax uses bare ex2
        const float scl = (z == 0) ? 0.125f * 1.44269504088896f : 1.0f;
        #pragma unroll
        for (int i = 0; i < 2; i++)
            #pragma unroll
            for (int t = 0; t < 8; t++)
                #pragma unroll
                for (int rr = 0; rr < 2; rr++) {
                    int m = m0 + 32*wm + 16*i + (l>>2) + 8*rr;
                    int n = n0 + 64*wn + 8*t + 2*(l&3);
                    uint32_t h = pack2h(acc[i][t][2*rr]*scl, acc[i][t][2*rr+1]*scl);
                    int b = m >> 11, s = m & 2047, hh = n >> 6, d = n & 63;
                    size_t idx = ((((size_t)b*NHEADS + hh)*SEQ) + s)*HDIM + d;
                    *(uint32_t*)(oh + idx) = h;
                }
    }
}

// ---------------------------------------------------------------------------
// Flash attention, plain fp16. CTA = 64 q-rows; 4 warps; 3 CTAs/SM.
// K-tile = 128 keys, static unrolls. Scores arrive in log2 domain (Q scaled);
// softmax uses bare ex2.approx (MUFU).
// ---------------------------------------------------------------------------
#define APITCH 144
#define AKPL   (128*APITCH)        // 18432 (one plane: 128 rows)
#define ASTAGE (2*AKPL)            // 36864 (K, V)
#define ASMEM  (2*ASTAGE)          // 73728

__global__ __launch_bounds__(128,3) void attn_kernel()
{
    extern __shared__ char sma[];
    const uint32_t sb = s2u(sma);
    const int tid = threadIdx.x, l = tid & 31, wid = tid >> 5;
    const int qt = 31 - (int)blockIdx.x;        // heavy tiles first
    const int bh = blockIdx.y;
    const int q0 = qt * 64;
    const int nkt = (q0 + 63)/128 + 1;          // 128-key tiles
    const size_t base = (size_t)bh * SEQ * HDIM;
    const __half *Qg = g_qkv + base;
    const __half *Kg = g_qkv + MATSZ + base;
    const __half *Vg = g_qkv + 2*(size_t)MATSZ + base;

    // ---- stream Q plane through stage-0 buffer, extract register frags ----
    #pragma unroll
    for (int i = 0; i < 4; i++) {
        int g = i*128 + tid;
        int row = (g >> 3) & 63, ch = g & 7;
        cpa16(sb + row*APITCH + ch*16, Qg + (size_t)(q0 + row)*HDIM + ch*8);
    }
    CPCOMMIT();
    CPWAIT0();
    __syncthreads();

    uint32_t qf[4][4];
    {
        int row = 16*wid + (l & 15);
        #pragma unroll
        for (int kc = 0; kc < 4; kc++) {
            int ko = kc*16 + ((l >> 4) << 3);
            uint32_t off = (uint32_t)(row*APITCH + ko*2);
            ldsm4(qf[kc][0],qf[kc][1],qf[kc][2],qf[kc][3], sb + off);
        }
    }
    __syncthreads();   // all warps done reading Q before buffer reuse

    auto load_kv = [&](int kt){
        const uint32_t stb = sb + (kt & 1)*ASTAGE;
        const int k0 = kt * 128;
        #pragma unroll
        for (int i = 0; i < 16; i++) {
            int g = i*128 + tid;
            int p = g >> 10, row = (g >> 3) & 127, ch = g & 7;  // p: 0 K, 1 V
            const __half* src = p ? Vg : Kg;
            cpa16(stb + p*AKPL + row*APITCH + ch*16,
                  src + (size_t)(k0 + row)*HDIM + ch*8);
        }
        CPCOMMIT();
    };
    load_kv(0);
    CPWAIT0();
    __syncthreads();

    float o[8][4];
    #pragma unroll
    for (int t = 0; t < 8; t++)
        #pragma unroll
        for (int j = 0; j < 4; j++) o[t][j] = 0.f;
    float mr0 = -1e30f, mr1 = -1e30f, lr0 = 0.f, lr1 = 0.f;
    const int qg0 = q0 + 16*wid + (l >> 2);
    const int qg1 = qg0 + 8;

    for (int kt = 0; kt < nkt; kt++) {
        if (kt + 1 < nkt) load_kv(kt + 1);
        const uint32_t stb = sb + (kt & 1)*ASTAGE;
        const int k0 = kt * 128;

        {
            // ---- S = Q K^T over 128 keys (16 n8-tiles) ----
            float s[16][4];
            #pragma unroll
            for (int t = 0; t < 16; t++)
                #pragma unroll
                for (int j = 0; j < 4; j++) s[t][j] = 0.f;
            #pragma unroll
            for (int kc = 0; kc < 4; kc++) {
                #pragma unroll
                for (int half = 0; half < 2; half++) {   // bf regs capped at 16
                    uint32_t bf[8][2];
                    #pragma unroll
                    for (int tp = 0; tp < 4; tp++) {
                        int nrow = half*64 + 16*tp + ((l>>4)<<3) + (l & 7);
                        int ko   = kc*16 + (((l>>3)&1) << 3);
                        uint32_t off = (uint32_t)(nrow*APITCH + ko*2);
                        ldsm4(bf[2*tp][0],bf[2*tp][1],bf[2*tp+1][0],bf[2*tp+1][1], stb + off);
                    }
                    #pragma unroll
                    for (int t = 0; t < 8; t++) mma_fp16(s[half*8 + t], qf[kc], bf[t]);
                }
            }
            // ---- causal mask (only near diagonal) ----
            if (k0 + 127 > qg0) {
                #pragma unroll
                for (int t = 0; t < 16; t++) {
                    int kg = k0 + 8*t + 2*(l & 3);
                    if (kg     > qg0) s[t][0] = -1e30f;
                    if (kg + 1 > qg0) s[t][1] = -1e30f;
                    if (kg     > qg1) s[t][2] = -1e30f;
                    if (kg + 1 > qg1) s[t][3] = -1e30f;
                }
            }
            // ---- online softmax (log2 domain, bare ex2) ----
            float mx0 = -1e30f, mx1 = -1e30f;
            #pragma unroll
            for (int t = 0; t < 16; t++) {
                mx0 = fmaxf(mx0, fmaxf(s[t][0], s[t][1]));
                mx1 = fmaxf(mx1, fmaxf(s[t][2], s[t][3]));
            }
            mx0 = fmaxf(mx0, __shfl_xor_sync(0xffffffffu, mx0, 1));
            mx0 = fmaxf(mx0, __shfl_xor_sync(0xffffffffu, mx0, 2));
            mx1 = fmaxf(mx1, __shfl_xor_sync(0xffffffffu, mx1, 1));
            mx1 = fmaxf(mx1, __shfl_xor_sync(0xffffffffu, mx1, 2));
            float mn0 = fmaxf(mr0, mx0), mn1 = fmaxf(mr1, mx1);
            float a0 = ex2(mr0 - mn0), a1 = ex2(mr1 - mn1);
            mr0 = mn0; mr1 = mn1;
            float rs0 = 0.f, rs1 = 0.f;
            #pragma unroll
            for (int t = 0; t < 16; t++) {
                s[t][0] = ex2(s[t][0] - mn0);
                s[t][1] = ex2(s[t][1] - mn0);
                s[t][2] = ex2(s[t][2] - mn1);
                s[t][3] = ex2(s[t][3] - mn1);
                rs0 += s[t][0] + s[t][1];
                rs1 += s[t][2] + s[t][3];
            }
            rs0 += __shfl_xor_sync(0xffffffffu, rs0, 1);
            rs0 += __shfl_xor_sync(0xffffffffu, rs0, 2);
            rs1 += __shfl_xor_sync(0xffffffffu, rs1, 1);
            rs1 += __shfl_xor_sync(0xffffffffu, rs1, 2);
            lr0 = lr0*a0 + rs0;
            lr1 = lr1*a1 + rs1;
            #pragma unroll
            for (int t = 0; t < 8; t++) {
                o[t][0] *= a0; o[t][1] *= a0; o[t][2] *= a1; o[t][3] *= a1;
            }
            // ---- P -> fp16 A-fragments (registers only), 8 k16 chunks ----
            uint32_t ph[8][4];
            #pragma unroll
            for (int kc = 0; kc < 8; kc++) {
                int t0 = 2*kc, t1 = t0 + 1;
                ph[kc][0] = pack2h(s[t0][0], s[t0][1]);
                ph[kc][1] = pack2h(s[t0][2], s[t0][3]);
                ph[kc][2] = pack2h(s[t1][0], s[t1][1]);
                ph[kc][3] = pack2h(s[t1][2], s[t1][3]);
            }
            // ---- O += P V over 128 keys, V via ldmatrix.trans ----
            #pragma unroll
            for (int kc = 0; kc < 8; kc++) {
                uint32_t vf[8][2];
                #pragma unroll
                for (int tp = 0; tp < 4; tp++) {
                    int row = kc*16 + ((l>>3)&1)*8 + (l & 7);
                    int co  = 16*tp + ((l >> 4) << 3);
                    uint32_t off = (uint32_t)(row*APITCH + co*2);
                    ldsm4t(vf[2*tp][0],vf[2*tp][1],vf[2*tp+1][0],vf[2*tp+1][1], stb + AKPL + off);
                }
                #pragma unroll
                for (int t = 0; t < 8; t++) mma_fp16(o[t], ph[kc], vf[t]);
            }
        }
        if (kt + 1 < nkt) { CPWAIT0(); __syncthreads(); }
    }

    // ---- epilogue: normalize, write fp16 plane [B,S,E] ----
    const float inv0 = 1.f / lr0, inv1 = 1.f / lr1;
    const int b = bh >> 4, h = bh & 15;
    const int s0 = qg0, s1 = qg1;
    #pragma unroll
    for (int t = 0; t < 8; t++) {
        int d = 8*t + 2*(l & 3);
        int e = h*HDIM + d;
        *(uint32_t*)(g_a + ((size_t)b*SEQ + s0)*EMBED + e) =
            pack2h(o[t][0]*inv0, o[t][1]*inv0);
        *(uint32_t*)(g_a + ((size_t)b*SEQ + s1)*EMBED + e) =
            pack2h(o[t][2]*inv1, o[t][3]*inv1);
    }
}

// ---------------------------------------------------------------------------
extern "C" void kernel_launch(void* const* d_in, const int* in_sizes, int n_in,
                              void* d_out, int out_size)
{
    const float* x  = (const float*)d_in[0];
    const float* Wq = (const float*)d_in[1];
    const float* Wk = (const float*)d_in[2];
    const float* Wv = (const float*)d_in[3];
    const float* Wo = (const float*)d_in[4];
    const float* bo = (const float*)d_in[5];
    float* out = (float*)d_out;

    cudaFuncSetAttribute(gemm_kernel, cudaFuncAttributeMaxDynamicSharedMemorySize, GSMEM);
    cudaFuncSetAttribute(attn_kernel, cudaFuncAttributeMaxDynamicSharedMemorySize, ASMEM);

    prep_kernel<<<dim3(32, 32, 8), dim3(32, 8)>>>(x, Wq, Wk, Wv, Wo);

    gemm_kernel<<<dim3(4, 32, 3), 512, GSMEM>>>(nullptr, nullptr, 0);  // QKV
    attn_kernel<<<dim3(32, 32), 128, ASMEM>>>();                       // attention
    gemm_kernel<<<dim3(4, 32, 1), 512, GSMEM>>>(out, bo, 1);           // O-proj
}